// round 1
// baseline (speedup 1.0000x reference)
#include <cuda_runtime.h>

// ---------------- scratch (no allocs allowed) ----------------
__device__ float g_Q  [32 * 1500 * 8];   // [b][l][c], pre-scaled by SCALE*log2e
__device__ float g_K  [32 * 8 * 1500];   // [b][c][m]
__device__ float g_V  [32 * 8 * 1500];   // [b][c][m]
__device__ float g_ctx[32 * 8 * 1500];   // [b][c][l]
__device__ float g_h1 [32 * 32 * 376];   // [b][co][lo], row padded 374->376 for float4
__device__ float g_h2 [32 * 64 * 96];    // [b][co][lo], row padded 92->96

// ---------------- f32x2 helpers (Blackwell packed fp32) ----------------
typedef unsigned long long ull;

__device__ __forceinline__ ull pack2(float x, float y) {
    ull r; asm("mov.b64 %0, {%1, %2};" : "=l"(r) : "f"(x), "f"(y)); return r;
}
__device__ __forceinline__ float2 unpack2(ull v) {
    float2 f; asm("mov.b64 {%0, %1}, %2;" : "=f"(f.x), "=f"(f.y) : "l"(v)); return f;
}
__device__ __forceinline__ ull ffma2(ull a, ull b, ull c) {
    ull d; asm("fma.rn.f32x2 %0, %1, %2, %3;" : "=l"(d) : "l"(a), "l"(b), "l"(c)); return d;
}
__device__ __forceinline__ ull add2(ull a, ull b) {
    ull d; asm("add.rn.f32x2 %0, %1, %2;" : "=l"(d) : "l"(a), "l"(b)); return d;
}
__device__ __forceinline__ float ex2(float x) {
    float y; asm("ex2.approx.f32 %0, %1;" : "=f"(y) : "f"(x)); return y;
}

// ---------------- kernel 1: conv QKV projections ----------------
__global__ void qkv_kernel(const float* __restrict__ sig,
                           const float* __restrict__ wq, const float* __restrict__ bq,
                           const float* __restrict__ wk, const float* __restrict__ bk,
                           const float* __restrict__ wv, const float* __restrict__ bv) {
    int idx = blockIdx.x * blockDim.x + threadIdx.x;
    if (idx >= 32 * 1500) return;
    int l = idx % 1500;
    int b = idx / 1500;
    float s0  = sig[idx];
    float sm1 = (l > 0)    ? sig[idx - 1] : 0.f;
    float sp1 = (l < 1499) ? sig[idx + 1] : 0.f;
    const float QS = 1.44269504088896341f * rsqrtf(1500.0f);  // log2(e)/sqrt(1500)
#pragma unroll
    for (int c = 0; c < 8; c++) {
        float q = fmaf(wq[c*3], sm1, fmaf(wq[c*3+1], s0, fmaf(wq[c*3+2], sp1, bq[c])));
        float k = fmaf(wk[c*3], sm1, fmaf(wk[c*3+1], s0, fmaf(wk[c*3+2], sp1, bk[c])));
        float v = fmaf(wv[c*3], sm1, fmaf(wv[c*3+1], s0, fmaf(wv[c*3+2], sp1, bv[c])));
        g_Q[idx * 8 + c]          = q * QS;
        g_K[(b*8 + c)*1500 + l]   = k;
        g_V[(b*8 + c)*1500 + l]   = v;
    }
}

// ---------------- kernel 2: fused attention ----------------
// Grid (32, 9), 256 threads. K,V for one batch staged in smem (96 KB).
// Each warp handles 4 query rows at a time, packed as two f32x2 pairs.
// Scores are bounded (|s| < ~0.15) so softmax needs no max subtraction.
__global__ void attn_kernel() {
    extern __shared__ float sm[];
    float* sK = sm;
    float* sV = sm + 12000;
    int b = blockIdx.x;

    const float4* k4 = (const float4*)(g_K + b * 12000);
    const float4* v4 = (const float4*)(g_V + b * 12000);
    float4* sK4 = (float4*)sK;
    float4* sV4 = (float4*)sV;
    for (int i = threadIdx.x; i < 3000; i += blockDim.x) {
        sK4[i] = k4[i];
        sV4[i] = v4[i];
    }
    __syncthreads();

    int warp = threadIdx.x >> 5;
    int lane = threadIdx.x & 31;
    const ull ONE2 = pack2(1.f, 1.f);

    for (int chunk = blockIdx.y * 8 + warp; chunk < 375; chunk += gridDim.y * 8) {
        int r0 = chunk * 4;
        const float* qp = g_Q + (b * 1500 + r0) * 8;
        ull qA[8], qB[8];
#pragma unroll
        for (int c = 0; c < 8; c++) {
            qA[c] = pack2(qp[c],      qp[8 + c]);   // rows r0, r0+1
            qB[c] = pack2(qp[16 + c], qp[24 + c]);  // rows r0+2, r0+3
        }
        ull accA[8], accB[8];
#pragma unroll
        for (int c = 0; c < 8; c++) { accA[c] = 0ull; accB[c] = 0ull; }
        ull denA = 0ull, denB = 0ull;

        for (int m = lane; m < 1500; m += 32) {
            ull sA = 0ull, sB = 0ull;
#pragma unroll
            for (int c = 0; c < 8; c++) {
                float kv = sK[c * 1500 + m];
                ull kk = pack2(kv, kv);
                sA = ffma2(qA[c], kk, sA);
                sB = ffma2(qB[c], kk, sB);
            }
            float2 fA = unpack2(sA), fB = unpack2(sB);
            ull pA = pack2(ex2(fA.x), ex2(fA.y));   // exp(score)
            ull pB = pack2(ex2(fB.x), ex2(fB.y));
            denA = ffma2(pA, ONE2, denA);
            denB = ffma2(pB, ONE2, denB);
#pragma unroll
            for (int c = 0; c < 8; c++) {
                float vv = sV[c * 1500 + m];
                ull v2 = pack2(vv, vv);
                accA[c] = ffma2(pA, v2, accA[c]);
                accB[c] = ffma2(pB, v2, accB[c]);
            }
        }

        // butterfly reduce across lanes (all lanes end with totals)
#pragma unroll
        for (int off = 16; off; off >>= 1) {
            denA = add2(denA, __shfl_xor_sync(0xffffffffu, denA, off));
            denB = add2(denB, __shfl_xor_sync(0xffffffffu, denB, off));
#pragma unroll
            for (int c = 0; c < 8; c++) {
                accA[c] = add2(accA[c], __shfl_xor_sync(0xffffffffu, accA[c], off));
                accB[c] = add2(accB[c], __shfl_xor_sync(0xffffffffu, accB[c], off));
            }
        }

        float2 dA = unpack2(denA), dB = unpack2(denB);
        float i0 = 1.f / dA.x, i1 = 1.f / dA.y, i2 = 1.f / dB.x, i3 = 1.f / dB.y;
#pragma unroll
        for (int c = 0; c < 8; c++) {
            if (lane == c) {
                float2 a  = unpack2(accA[c]);
                float2 bb = unpack2(accB[c]);
                float* cp = g_ctx + (b * 8 + c) * 1500 + r0;
                cp[0] = a.x * i0;
                cp[1] = a.y * i1;
                cp[2] = bb.x * i2;
                cp[3] = bb.y * i3;
            }
        }
    }
}

// ---------------- kernel 3: conv1 (8 -> 32 ch, k=8, stride 4) ----------------
// warp = (b, co, lo-tile); lanes = lo. Weights uniform per warp.
__global__ void conv1_kernel(const float* __restrict__ w1, const float* __restrict__ b1) {
    int gw   = (blockIdx.x * blockDim.x + threadIdx.x) >> 5;  // 0..12287
    int lane = threadIdx.x & 31;
    int tile = gw % 12;
    int co   = (gw / 12) % 32;
    int b    = gw / (12 * 32);
    int lo   = tile * 32 + lane;
    if (lo >= 374) return;
    float acc = b1[co];
    const float* wp = w1 + co * 64;
#pragma unroll
    for (int ci = 0; ci < 8; ci++) {
        const float4* xp = (const float4*)(g_ctx + (b * 8 + ci) * 1500 + 4 * lo);
        float4 x0 = xp[0], x1 = xp[1];
        const float* w = wp + ci * 8;
        acc += w[0]*x0.x + w[1]*x0.y + w[2]*x0.z + w[3]*x0.w
             + w[4]*x1.x + w[5]*x1.y + w[6]*x1.z + w[7]*x1.w;
    }
    g_h1[(b * 32 + co) * 376 + lo] = acc;
}

// ---------------- kernel 4: conv2 (32 -> 64 ch, k=8, stride 4) ----------------
__global__ void conv2_kernel(const float* __restrict__ w2, const float* __restrict__ b2) {
    int gw   = (blockIdx.x * blockDim.x + threadIdx.x) >> 5;  // 0..6143
    int lane = threadIdx.x & 31;
    int tile = gw % 3;
    int co   = (gw / 3) % 64;
    int b    = gw / (3 * 64);
    int lo   = tile * 32 + lane;
    if (lo >= 92) return;
    float acc = b2[co];
    const float* wp = w2 + co * 256;
#pragma unroll 8
    for (int ci = 0; ci < 32; ci++) {
        const float4* xp = (const float4*)(g_h1 + (b * 32 + ci) * 376 + 4 * lo);
        float4 x0 = xp[0], x1 = xp[1];
        const float* w = wp + ci * 8;
        acc += w[0]*x0.x + w[1]*x0.y + w[2]*x0.z + w[3]*x0.w
             + w[4]*x1.x + w[5]*x1.y + w[6]*x1.z + w[7]*x1.w;
    }
    g_h2[(b * 64 + co) * 96 + lo] = acc;
}

// ---------------- kernel 5: conv3 (64 -> 8 ch) + linear, fused per batch ----------------
__global__ void head_kernel(const float* __restrict__ w3, const float* __restrict__ b3,
                            const float* __restrict__ wl, const float* __restrict__ bl,
                            float* __restrict__ out) {
    __shared__ float flat[176];
    int b    = blockIdx.x;
    int warp = threadIdx.x >> 5;  // 8 warps: warp = co
    int lane = threadIdx.x & 31;

    if (lane < 22) {
        float acc = b3[warp];
        const float* wp = w3 + warp * 512;
#pragma unroll 8
        for (int ci = 0; ci < 64; ci++) {
            const float4* xp = (const float4*)(g_h2 + (b * 64 + ci) * 96 + 4 * lane);
            float4 x0 = xp[0], x1 = xp[1];
            const float* w = wp + ci * 8;
            acc += w[0]*x0.x + w[1]*x0.y + w[2]*x0.z + w[3]*x0.w
                 + w[4]*x1.x + w[5]*x1.y + w[6]*x1.z + w[7]*x1.w;
        }
        flat[warp * 22 + lane] = acc;  // reshape: flat[co*22 + lo]
    }
    __syncthreads();

    if (warp < 3) {
        float s = 0.f;
        for (int i = lane; i < 176; i += 32) s += wl[warp * 176 + i] * flat[i];
#pragma unroll
        for (int off = 16; off; off >>= 1) s += __shfl_xor_sync(0xffffffffu, s, off);
        if (lane == 0) out[b * 3 + warp] = s + bl[warp];
    }
}

// ---------------- launch ----------------
extern "C" void kernel_launch(void* const* d_in, const int* in_sizes, int n_in,
                              void* d_out, int out_size) {
    const float* signal = (const float*)d_in[0];
    const float* wq = (const float*)d_in[1];
    const float* bq = (const float*)d_in[2];
    const float* wk = (const float*)d_in[3];
    const float* bk = (const float*)d_in[4];
    const float* wv = (const float*)d_in[5];
    const float* bv = (const float*)d_in[6];
    const float* w1 = (const float*)d_in[7];
    const float* b1 = (const float*)d_in[8];
    const float* w2 = (const float*)d_in[9];
    const float* b2 = (const float*)d_in[10];
    const float* w3 = (const float*)d_in[11];
    const float* b3 = (const float*)d_in[12];
    const float* wl = (const float*)d_in[13];
    const float* bl = (const float*)d_in[14];
    float* out = (float*)d_out;

    qkv_kernel<<<(32 * 1500 + 255) / 256, 256>>>(signal, wq, bq, wk, bk, wv, bv);

    cudaFuncSetAttribute(attn_kernel, cudaFuncAttributeMaxDynamicSharedMemorySize, 96 * 1024);
    attn_kernel<<<dim3(32, 9), 256, 96000>>>();

    conv1_kernel<<<1536, 256>>>(w1, b1);   // 12288 warps
    conv2_kernel<<<768, 256>>>(w2, b2);    // 6144 warps
    head_kernel<<<32, 256>>>(w3, b3, wl, bl, out);
}

// round 2
// speedup vs baseline: 1.0296x; 1.0296x over previous
#include <cuda_runtime.h>

// ---------------- scratch (no allocs allowed) ----------------
__device__ float g_Q  [32 * 1500 * 8];   // [b][l][c], pre-scaled by SCALE*log2e
__device__ float g_K  [32 * 8 * 1500];   // [b][c][m]
__device__ float g_V  [32 * 8 * 1500];   // [b][c][m]
__device__ float g_ctx[32 * 8 * 1500];   // [b][c][l]
__device__ float g_h1 [32 * 32 * 376];   // [b][co][lo], row padded 374->376
__device__ float g_h2 [32 * 64 * 96];    // [b][co][lo], row padded 92->96

// ---------------- f32x2 helpers (Blackwell packed fp32) ----------------
typedef unsigned long long ull;

__device__ __forceinline__ ull pack2(float x, float y) {
    ull r; asm("mov.b64 %0, {%1, %2};" : "=l"(r) : "f"(x), "f"(y)); return r;
}
__device__ __forceinline__ float2 unpack2(ull v) {
    float2 f; asm("mov.b64 {%0, %1}, %2;" : "=f"(f.x), "=f"(f.y) : "l"(v)); return f;
}
__device__ __forceinline__ ull ffma2(ull a, ull b, ull c) {
    ull d; asm("fma.rn.f32x2 %0, %1, %2, %3;" : "=l"(d) : "l"(a), "l"(b), "l"(c)); return d;
}
__device__ __forceinline__ ull add2(ull a, ull b) {
    ull d; asm("add.rn.f32x2 %0, %1, %2;" : "=l"(d) : "l"(a), "l"(b)); return d;
}
__device__ __forceinline__ float ex2(float x) {
    float y; asm("ex2.approx.f32 %0, %1;" : "=f"(y) : "f"(x)); return y;
}

// ---------------- kernel 1: conv QKV projections ----------------
__global__ void qkv_kernel(const float* __restrict__ sig,
                           const float* __restrict__ wq, const float* __restrict__ bq,
                           const float* __restrict__ wk, const float* __restrict__ bk,
                           const float* __restrict__ wv, const float* __restrict__ bv) {
    int idx = blockIdx.x * blockDim.x + threadIdx.x;
    if (idx >= 32 * 1500) return;
    int l = idx % 1500;
    int b = idx / 1500;
    float s0  = sig[idx];
    float sm1 = (l > 0)    ? sig[idx - 1] : 0.f;
    float sp1 = (l < 1499) ? sig[idx + 1] : 0.f;
    const float QS = 1.44269504088896341f * rsqrtf(1500.0f);  // log2(e)/sqrt(1500)
#pragma unroll
    for (int c = 0; c < 8; c++) {
        float q = fmaf(wq[c*3], sm1, fmaf(wq[c*3+1], s0, fmaf(wq[c*3+2], sp1, bq[c])));
        float k = fmaf(wk[c*3], sm1, fmaf(wk[c*3+1], s0, fmaf(wk[c*3+2], sp1, bk[c])));
        float v = fmaf(wv[c*3], sm1, fmaf(wv[c*3+1], s0, fmaf(wv[c*3+2], sp1, bv[c])));
        g_Q[idx * 8 + c]          = q * QS;
        g_K[(b*8 + c)*1500 + l]   = k;
        g_V[(b*8 + c)*1500 + l]   = v;
    }
}

// ---------------- kernel 2: fused attention (f32x2 packed over m) ----------------
// Grid (32, 9), 384 threads. K,V for one batch in smem (96 KB, viewed as ull pairs).
// Each warp handles 4 query rows; each lane processes 2 adjacent keys per step,
// loaded directly as LDS.64 pairs -> no pack instructions in the inner loop.
// |score| < ~0.15 so softmax needs no max subtraction.
__global__ void __launch_bounds__(384, 1) attn_kernel() {
    extern __shared__ float smbuf[];
    float* sK = smbuf;          // 12000 floats
    float* sV = smbuf + 12000;  // 12000 floats
    int b = blockIdx.x;

    const float4* k4 = (const float4*)(g_K + b * 12000);
    const float4* v4 = (const float4*)(g_V + b * 12000);
    float4* sK4 = (float4*)sK;
    float4* sV4 = (float4*)sV;
    for (int i = threadIdx.x; i < 3000; i += 384) {
        sK4[i] = k4[i];
        sV4[i] = v4[i];
    }
    __syncthreads();

    const ull* sK2 = (const ull*)sK;   // [c][750] pairs
    const ull* sV2 = (const ull*)sV;
    int warp = threadIdx.x >> 5;
    int lane = threadIdx.x & 31;

    for (int chunk = blockIdx.y * 12 + warp; chunk < 375; chunk += 108) {
        int r0 = chunk * 4;
        const float* qp = g_Q + (b * 1500 + r0) * 8;
        ull qq[4][8];
#pragma unroll
        for (int r = 0; r < 4; r++)
#pragma unroll
            for (int c = 0; c < 8; c++) {
                float q = qp[r * 8 + c];
                qq[r][c] = pack2(q, q);
            }

        ull acc[4][8];
        ull den[4];
#pragma unroll
        for (int r = 0; r < 4; r++) {
            den[r] = 0ull;
#pragma unroll
            for (int c = 0; c < 8; c++) acc[r][c] = 0ull;
        }

        for (int p = lane; p < 750; p += 32) {
            ull s2[4] = {0ull, 0ull, 0ull, 0ull};
#pragma unroll
            for (int c = 0; c < 8; c++) {
                ull k2 = sK2[c * 750 + p];
#pragma unroll
                for (int r = 0; r < 4; r++) s2[r] = ffma2(qq[r][c], k2, s2[r]);
            }
            ull p2[4];
#pragma unroll
            for (int r = 0; r < 4; r++) {
                float2 f = unpack2(s2[r]);
                p2[r] = pack2(ex2(f.x), ex2(f.y));
                den[r] = add2(den[r], p2[r]);
            }
#pragma unroll
            for (int c = 0; c < 8; c++) {
                ull v2 = sV2[c * 750 + p];
#pragma unroll
                for (int r = 0; r < 4; r++) acc[r][c] = ffma2(p2[r], v2, acc[r][c]);
            }
        }

        // collapse f32x2 halves to scalars, then butterfly-reduce across lanes
        float a[4][8], d[4];
#pragma unroll
        for (int r = 0; r < 4; r++) {
            float2 f = unpack2(den[r]);
            d[r] = f.x + f.y;
#pragma unroll
            for (int c = 0; c < 8; c++) {
                float2 g = unpack2(acc[r][c]);
                a[r][c] = g.x + g.y;
            }
        }
#pragma unroll
        for (int off = 16; off; off >>= 1) {
#pragma unroll
            for (int r = 0; r < 4; r++) {
                d[r] += __shfl_xor_sync(0xffffffffu, d[r], off);
#pragma unroll
                for (int c = 0; c < 8; c++)
                    a[r][c] += __shfl_xor_sync(0xffffffffu, a[r][c], off);
            }
        }

        float inv[4];
#pragma unroll
        for (int r = 0; r < 4; r++) inv[r] = 1.f / d[r];
#pragma unroll
        for (int c = 0; c < 8; c++) {
            if (lane == c) {
                float* cp = g_ctx + (b * 8 + c) * 1500 + r0;
#pragma unroll
                for (int r = 0; r < 4; r++) cp[r] = a[r][c] * inv[r];
            }
        }
    }
}

// ---------------- kernel 3: conv1 (8 -> 32 ch, k=8, stride 4), smem-staged ----------------
// Grid (32, 12), 256 threads. Block = (batch, 32-wide lo tile).
__global__ void conv1_kernel(const float* __restrict__ w1, const float* __restrict__ b1) {
    __shared__ __align__(16) float xs[8][136];   // x slice: 132 used + pad
    __shared__ __align__(16) float ws[2048];     // full w1 (32*8*8)
    int b = blockIdx.x, t = blockIdx.y;

    for (int i = threadIdx.x; i < 2048; i += 256) ws[i] = w1[i];
    for (int i = threadIdx.x; i < 8 * 136; i += 256) {
        int ci = i / 136, j = i % 136;
        int gx = 128 * t + j;
        xs[ci][j] = (gx < 1500) ? g_ctx[(b * 8 + ci) * 1500 + gx] : 0.f;
    }
    __syncthreads();

    int warp = threadIdx.x >> 5;
    int lane = threadIdx.x & 31;
    int lo   = t * 32 + lane;
    int cob  = warp * 4;

    const ull* xsu = (const ull*)&xs[0][0];   // per-ci row: 68 ull
    const ull* wsu = (const ull*)ws;          // [co][ci][kpair]: co*32 + ci*4 + kp

    ull acc[4] = {0ull, 0ull, 0ull, 0ull};
#pragma unroll
    for (int ci = 0; ci < 8; ci++) {
        ull x[4];
#pragma unroll
        for (int kp = 0; kp < 4; kp++) x[kp] = xsu[ci * 68 + 2 * lane + kp];
#pragma unroll
        for (int co = 0; co < 4; co++)
#pragma unroll
            for (int kp = 0; kp < 4; kp++)
                acc[co] = ffma2(wsu[(cob + co) * 32 + ci * 4 + kp], x[kp], acc[co]);
    }
    if (lo < 374) {
#pragma unroll
        for (int co = 0; co < 4; co++) {
            float2 f = unpack2(acc[co]);
            g_h1[(b * 32 + cob + co) * 376 + lo] = f.x + f.y + b1[cob + co];
        }
    }
}

// ---------------- kernel 4: conv2 (32 -> 64 ch, k=8, stride 4), smem-staged ----------------
// Grid (32, 3), 256 threads, dynamic smem: xs (32*136 floats) + ws (16384 floats).
__global__ void conv2_kernel(const float* __restrict__ w2, const float* __restrict__ b2) {
    extern __shared__ float smbuf[];
    float* xs = smbuf;              // [32][136]
    float* ws = smbuf + 32 * 136;   // 16384 floats
    int b = blockIdx.x, t = blockIdx.y;

    const float4* w4 = (const float4*)w2;
    float4* ws4 = (float4*)ws;
    for (int i = threadIdx.x; i < 4096; i += 256) ws4[i] = w4[i];
    for (int i = threadIdx.x; i < 32 * 136; i += 256) {
        int ci = i / 136, j = i % 136;
        int gx = 128 * t + j;
        xs[i] = (gx < 374) ? g_h1[(b * 32 + ci) * 376 + gx] : 0.f;
    }
    __syncthreads();

    int warp = threadIdx.x >> 5;
    int lane = threadIdx.x & 31;
    int lo   = t * 32 + lane;
    int cob  = warp * 8;

    const ull* xsu = (const ull*)xs;   // per-ci row: 68 ull
    const ull* wsu = (const ull*)ws;   // [co][ci][kpair]: co*128 + ci*4 + kp

    ull acc[8] = {0ull,0ull,0ull,0ull,0ull,0ull,0ull,0ull};
#pragma unroll 4
    for (int ci = 0; ci < 32; ci++) {
        ull x[4];
#pragma unroll
        for (int kp = 0; kp < 4; kp++) x[kp] = xsu[ci * 68 + 2 * lane + kp];
#pragma unroll
        for (int co = 0; co < 8; co++)
#pragma unroll
            for (int kp = 0; kp < 4; kp++)
                acc[co] = ffma2(wsu[(cob + co) * 128 + ci * 4 + kp], x[kp], acc[co]);
    }
    if (lo < 92) {
#pragma unroll
        for (int co = 0; co < 8; co++) {
            float2 f = unpack2(acc[co]);
            g_h2[(b * 64 + cob + co) * 96 + lo] = f.x + f.y + b2[cob + co];
        }
    }
}

// ---------------- kernel 5: conv3 (64 -> 8 ch) + linear, fused per batch ----------------
__global__ void head_kernel(const float* __restrict__ w3, const float* __restrict__ b3,
                            const float* __restrict__ wl, const float* __restrict__ bl,
                            float* __restrict__ out) {
    __shared__ float flat[176];
    int b    = blockIdx.x;
    int warp = threadIdx.x >> 5;  // 8 warps: warp = co
    int lane = threadIdx.x & 31;

    if (lane < 22) {
        float acc = b3[warp];
        const float* wp = w3 + warp * 512;
#pragma unroll 8
        for (int ci = 0; ci < 64; ci++) {
            const float4* xp = (const float4*)(g_h2 + (b * 64 + ci) * 96 + 4 * lane);
            float4 x0 = xp[0], x1 = xp[1];
            const float* w = wp + ci * 8;
            acc += w[0]*x0.x + w[1]*x0.y + w[2]*x0.z + w[3]*x0.w
                 + w[4]*x1.x + w[5]*x1.y + w[6]*x1.z + w[7]*x1.w;
        }
        flat[warp * 22 + lane] = acc;
    }
    __syncthreads();

    if (warp < 3) {
        float s = 0.f;
        for (int i = lane; i < 176; i += 32) s += wl[warp * 176 + i] * flat[i];
#pragma unroll
        for (int off = 16; off; off >>= 1) s += __shfl_xor_sync(0xffffffffu, s, off);
        if (lane == 0) out[b * 3 + warp] = s + bl[warp];
    }
}

// ---------------- launch ----------------
extern "C" void kernel_launch(void* const* d_in, const int* in_sizes, int n_in,
                              void* d_out, int out_size) {
    const float* signal = (const float*)d_in[0];
    const float* wq = (const float*)d_in[1];
    const float* bq = (const float*)d_in[2];
    const float* wk = (const float*)d_in[3];
    const float* bk = (const float*)d_in[4];
    const float* wv = (const float*)d_in[5];
    const float* bv = (const float*)d_in[6];
    const float* w1 = (const float*)d_in[7];
    const float* b1 = (const float*)d_in[8];
    const float* w2 = (const float*)d_in[9];
    const float* b2 = (const float*)d_in[10];
    const float* w3 = (const float*)d_in[11];
    const float* b3 = (const float*)d_in[12];
    const float* wl = (const float*)d_in[13];
    const float* bl = (const float*)d_in[14];
    float* out = (float*)d_out;

    qkv_kernel<<<(32 * 1500 + 255) / 256, 256>>>(signal, wq, bq, wk, bk, wv, bv);

    cudaFuncSetAttribute(attn_kernel, cudaFuncAttributeMaxDynamicSharedMemorySize, 96 * 1024);
    attn_kernel<<<dim3(32, 9), 384, 96000>>>();

    conv1_kernel<<<dim3(32, 12), 256>>>(w1, b1);

    cudaFuncSetAttribute(conv2_kernel, cudaFuncAttributeMaxDynamicSharedMemorySize, 84 * 1024);
    conv2_kernel<<<dim3(32, 3), 256, (32 * 136 + 16384) * 4>>>(w2, b2);

    head_kernel<<<32, 256>>>(w3, b3, wl, bl, out);
}